// round 13
// baseline (speedup 1.0000x reference)
#include <cuda_runtime.h>
#include <cuda_bf16.h>
#include <cstdint>

#define AA 5
#define THREADS 512
#define ROWS_PB 160
#define GROUPS_PB 32
#define NBLOCKS 4096

// ---------------- precomputed fused weights ---------------------------------
__device__ float    g_bqk  [AA][96];
__device__ float    g_bvo  [AA][96];
// extra weights, MMA-fragment layout: [(tile*6+ks)*32 + lane] = (bh0,bh1,bl0,bl1)
__device__ uint4    g_EWf[34*6*32];
// unified attention weights (qk cols 0-95, vo 96-191), fragment layout per a:
// [a*1536 + (n*2+ks)*32 + lane],  n = col-tile 0..23
__device__ uint4    g_WAf[AA*24*2*32];

__device__ __forceinline__ void split_bf16(float v, float& h, float& l) {
    h = __bfloat162float(__float2bfloat16_rn(v));
    l = v - h;
}

// pack: lo_e -> bits[15:0], hi_e -> bits[31:16]
__device__ __forceinline__ uint32_t packbf(float lo_e, float hi_e) {
    uint32_t r;
    asm("cvt.rn.bf16x2.f32 %0, %1, %2;" : "=r"(r) : "f"(hi_e), "f"(lo_e));
    return r;
}

__device__ __forceinline__ void mma16(float* d,
                                      uint32_t a0, uint32_t a1, uint32_t a2, uint32_t a3,
                                      uint32_t b0, uint32_t b1) {
    asm volatile("mma.sync.aligned.m16n8k16.row.col.f32.bf16.bf16.f32 "
                 "{%0,%1,%2,%3}, {%4,%5,%6,%7}, {%8,%9}, {%0,%1,%2,%3};"
                 : "+f"(d[0]), "+f"(d[1]), "+f"(d[2]), "+f"(d[3])
                 : "r"(a0), "r"(a1), "r"(a2), "r"(a3), "r"(b0), "r"(b1));
}

// ---------------------------- prep kernel ----------------------------------
#define PREP_T 256

// write one (col j_glob in 0..191, word w in 0..15) entry into g_WAf fragments
__device__ __forceinline__ void waf_write(int a, int j_glob, int w,
                                          float acc0, float acc1)
{
    float h0,l0,h1,l1;
    split_bf16(acc0, h0, l0); split_bf16(acc1, h1, l1);
    int n  = j_glob >> 3;
    int ks = w >> 3;
    int wp = w & 7;
    uint32_t* fr = (uint32_t*)&g_WAf[a*1536 + (n*2+ks)*32 + (j_glob&7)*4 + (wp&3)];
    fr[wp>>2]       = packbf(h0, h1);
    fr[2 + (wp>>2)] = packbf(l0, l1);
}

// blocks 0-9: qk (a = bid>>1, j-half = bid&1)
// blocks 10-19: vo ((a,h) = bid-10)
// blocks 20-27: extra (part = bid-20 of 8)
__global__ void prep_kernel(const float* __restrict__ agg_W,
                            const float* __restrict__ agg_b,
                            const float* __restrict__ ipw,
                            const float* __restrict__ ipb,
                            const float* __restrict__ out_w,
                            const float* __restrict__ extra_w)
{
    int bid = blockIdx.x;
    if (bid < 2*AA) {
        int a  = bid >> 1;
        int jh = bid & 1;                  // j in [jh*48, jh*48+48)
        __shared__ float sW[48*32];
        for (int i = threadIdx.x; i < 48*32; i += PREP_T)
            sW[i] = agg_W[a*1536 + i];
        __syncthreads();
        for (int o = threadIdx.x; o < 48*16; o += PREP_T) {
            int j = jh*48 + (o >> 4), w = o & 15;
            float acc0 = 0.f, acc1 = 0.f;
            #pragma unroll 4
            for (int e = 0; e < 48; e++) {
                float wv = ipw[j*48+e];
                acc0 += wv * sW[e*32 + 2*w];
                acc1 += wv * sW[e*32 + 2*w+1];
            }
            waf_write(a, j, w, acc0, acc1);
        }
        for (int jj = threadIdx.x; jj < 48; jj += PREP_T) {
            int j = jh*48 + jj;
            float acc = ipb[j];
            for (int e = 0; e < 48; e++)
                acc += ipw[j*48+e] * agg_b[a*48+e];
            g_bqk[a][j] = acc;
        }
    } else if (bid < 2*AA + 2*AA) {
        int a = (bid - 2*AA) >> 1;
        int h = (bid - 2*AA) & 1;
        __shared__ float sW[48*32];
        __shared__ float Wv[24][32];
        __shared__ float bv[24];
        for (int i = threadIdx.x; i < 48*32; i += PREP_T)
            sW[i] = agg_W[a*1536 + i];
        __syncthreads();
        for (int o = threadIdx.x; o < 24*32; o += PREP_T) {
            int d = o >> 5, c = o & 31;
            int row = 96 + h*24 + d;
            float acc = 0.f;
            #pragma unroll 4
            for (int e = 0; e < 48; e++)
                acc += ipw[row*48+e] * sW[e*32 + c];
            Wv[d][c] = acc;
        }
        for (int d = threadIdx.x; d < 24; d += PREP_T) {
            int row = 96 + h*24 + d;
            float acc = ipb[row];
            for (int e = 0; e < 48; e++)
                acc += ipw[row*48+e] * agg_b[a*48+e];
            bv[d] = acc;
        }
        __syncthreads();
        for (int o = threadIdx.x; o < 48*16; o += PREP_T) {
            int e = o >> 4, w = o & 15;
            float acc0 = 0.f, acc1 = 0.f;
            #pragma unroll
            for (int d = 0; d < 24; d++) {
                float ow = out_w[e*48 + h*24 + d];
                acc0 += Wv[d][2*w]   * ow;
                acc1 += Wv[d][2*w+1] * ow;
            }
            waf_write(a, 96 + h*48 + e, w, acc0, acc1);
        }
        for (int e = threadIdx.x; e < 48; e += PREP_T) {
            float acc = 0.f;
            for (int d = 0; d < 24; d++)
                acc += bv[d] * out_w[e*48 + h*24 + d];
            g_bvo[a][h*48 + e] = acc;
        }
    } else {
        // extra_w -> fragment layout; 8 blocks cover 34*6*32 = 6528 uint4
        int part = bid - 4*AA;                // 0..7
        int beg = part * 816;
        int end = beg + 816;
        for (int o = beg + threadIdx.x; o < end; o += PREP_T) {
            int lane = o & 31;
            int tk   = o >> 5;
            int ks   = tk % 6;
            int t    = tk / 6;
            int g4   = lane >> 2, t4 = lane & 3;
            int row  = t*8 + g4;              // output col (0..271)
            int w0   = ks*8 + t4;
            float v00 = extra_w[row*96 + 2*w0];
            float v01 = extra_w[row*96 + 2*w0 + 1];
            float v10 = extra_w[row*96 + 2*(w0+4)];
            float v11 = extra_w[row*96 + 2*(w0+4) + 1];
            float h00,l00,h01,l01,h10,l10,h11,l11;
            split_bf16(v00,h00,l00); split_bf16(v01,h01,l01);
            split_bf16(v10,h10,l10); split_bf16(v11,h11,l11);
            g_EWf[o] = make_uint4(packbf(h00,h01), packbf(h10,h11),
                                  packbf(l00,l01), packbf(l10,l11));
        }
    }
}

// ---------------------------- main kernel ----------------------------------
// Shared layout (32-bit words):
//   qk : fp32 D[160x192]; row r at (r/5)*1008 + (r%5)*200 (16B aligned)
//   pb : 32 x 52 fp32 softmax probs
#define GRP 1008
#define SM_QK  0
#define SM_PB  32256
#define SM_WORDS 33920           // 135680 bytes

__device__ __forceinline__ long row_xoff(int r)
{
    int a  = (r >> 12) % 5;
    int tx = (r / 20480) * 4096 + (r & 4095);
    return (long)tx * 256 + a * 32;
}

// load the A fragments (2 k-steps) for m-tile mt from global x
__device__ __forceinline__ void load_afrag(const float* __restrict__ x,
                                           int r0, int mt, int g4, int t4,
                                           uint32_t ah[2][4], uint32_t al[2][4])
{
    const float* xA = x + row_xoff(r0 + mt*16 + g4);
    const float* xB = x + row_xoff(r0 + mt*16 + g4 + 8);
    #pragma unroll
    for (int ks = 0; ks < 2; ks++) {
        int c0 = (ks*8 + t4)*2;
        float2 vA0 = *(const float2*)(xA + c0);
        float2 vA2 = *(const float2*)(xA + c0 + 8);
        float2 vB0 = *(const float2*)(xB + c0);
        float2 vB2 = *(const float2*)(xB + c0 + 8);
        float h0,l0,h1,l1;
        split_bf16(vA0.x,h0,l0); split_bf16(vA0.y,h1,l1);
        ah[ks][0] = packbf(h0,h1); al[ks][0] = packbf(l0,l1);
        split_bf16(vB0.x,h0,l0); split_bf16(vB0.y,h1,l1);
        ah[ks][1] = packbf(h0,h1); al[ks][1] = packbf(l0,l1);
        split_bf16(vA2.x,h0,l0); split_bf16(vA2.y,h1,l1);
        ah[ks][2] = packbf(h0,h1); al[ks][2] = packbf(l0,l1);
        split_bf16(vB2.x,h0,l0); split_bf16(vB2.y,h1,l1);
        ah[ks][3] = packbf(h0,h1); al[ks][3] = packbf(l0,l1);
    }
}

// load + pack the extra-pipeline A fragments for one 16-token tile
__device__ __forceinline__ void load_efrag(const float* __restrict__ xb,
                                           int t4,
                                           uint32_t Ah[6][4], uint32_t Al[6][4])
{
    #pragma unroll
    for (int ks = 0; ks < 6; ks++) {
        int c0 = (ks*8 + t4)*2;
        float2 v0 = *(const float2*)(xb + c0);
        float2 v2 = *(const float2*)(xb + c0 + 8);
        float2 v1 = *(const float2*)(xb + 2048 + c0);
        float2 v3 = *(const float2*)(xb + 2048 + c0 + 8);
        float h0,l0,h1,l1;
        split_bf16(v0.x,h0,l0); split_bf16(v0.y,h1,l1);
        Ah[ks][0] = packbf(h0,h1); Al[ks][0] = packbf(l0,l1);
        split_bf16(v1.x,h0,l0); split_bf16(v1.y,h1,l1);
        Ah[ks][1] = packbf(h0,h1); Al[ks][1] = packbf(l0,l1);
        split_bf16(v2.x,h0,l0); split_bf16(v2.y,h1,l1);
        Ah[ks][2] = packbf(h0,h1); Al[ks][2] = packbf(l0,l1);
        split_bf16(v3.x,h0,l0); split_bf16(v3.y,h1,l1);
        Ah[ks][3] = packbf(h0,h1); Al[ks][3] = packbf(l0,l1);
    }
}

// process attention GEMM sels [sbeg,send) of ONE m-tile mt:
// sel -> half=sel>>2 (0 qk | 1 vo), ng3=sel&3 (24-col group)
__device__ __forceinline__ void do_mt(const float* __restrict__ x,
                                      float* __restrict__ qk,
                                      int mt, int sbeg, int send,
                                      int r0, int Bnd, bool has_b,
                                      int a_lo, int a_hi,
                                      int g4, int t4, int lane)
{
    bool hiset = has_b && (r0 + mt*16) >= Bnd;
    int a_t = hiset ? a_hi : a_lo;
    uint32_t ah[2][4], al[2][4];
    load_afrag(x, r0, mt, g4, t4, ah, al);
    const uint4* wf = g_WAf + a_t*1536;

    int R0 = mt*16 + g4;
    int R1 = R0 + 8;
    int off0 = (R0/5)*GRP + (R0%5)*200;
    int off1 = (R1/5)*GRP + (R1%5)*200;

    #pragma unroll 1
    for (int sel = sbeg; sel < send; sel++) {
        int half = sel >> 2, ng3 = sel & 3;
        float acc[3][4];
        #pragma unroll
        for (int nj = 0; nj < 3; nj++)
            #pragma unroll
            for (int q = 0; q < 4; q++) acc[nj][q] = 0.f;
        #pragma unroll
        for (int ks = 0; ks < 2; ks++) {
            #pragma unroll
            for (int nj = 0; nj < 3; nj++) {
                int n = half*12 + ng3*3 + nj;
                uint4 bv = wf[(n*2+ks)*32 + lane];
                mma16(acc[nj], ah[ks][0],ah[ks][1],ah[ks][2],ah[ks][3], bv.x, bv.y);
                mma16(acc[nj], ah[ks][0],ah[ks][1],ah[ks][2],ah[ks][3], bv.z, bv.w);
                mma16(acc[nj], al[ks][0],al[ks][1],al[ks][2],al[ks][3], bv.x, bv.y);
            }
        }
        const float* bias = half ? g_bvo[a_t] : g_bqk[a_t];
        #pragma unroll
        for (int nj = 0; nj < 3; nj++) {
            int c96 = ng3*24 + nj*8 + 2*t4;
            float b0 = bias[c96], b1 = bias[c96+1];
            int col = half*96 + c96;
            *(float2*)&qk[off0 + col] = make_float2(acc[nj][0]+b0, acc[nj][1]+b1);
            *(float2*)&qk[off1 + col] = make_float2(acc[nj][2]+b0, acc[nj][3]+b1);
        }
    }
}

__global__ void __launch_bounds__(THREADS, 1)
main_kernel(const float* __restrict__ x,
            const float* __restrict__ extra_b,
            const float* __restrict__ out_b,
            float* __restrict__ out)
{
    extern __shared__ float sm[];
    float* qk = sm + SM_QK;
    float* pb = sm + SM_PB;

    const int tid  = threadIdx.x;
    const int lane = tid & 31;
    const int warp = tid >> 5;       // 0..15
    const int g4   = lane >> 2;
    const int t4   = lane & 3;

    const int r0    = blockIdx.x * ROWS_PB;
    const int m0tok = blockIdx.x * GROUPS_PB;

    const int  blk4k = r0 >> 12;
    const int  a_lo  = blk4k % 5;
    const int  Bnd   = (blk4k + 1) << 12;
    const bool has_b = (r0 + ROWS_PB) > Bnd;
    const int  a_hi  = has_b ? ((a_lo + 1) % 5) : a_lo;

    if (warp >= 8) {
        // =============== E-WARPS =============================================
        int ew = warp - 8;               // 0..7

        // 1) prefetch extra A fragments for token tile 0 (48 regs)
        uint32_t Ah0[6][4], Al0[6][4];
        load_efrag(x + (long)(m0tok + g4)*256 + 160, t4, Ah0, Al0);

        // 2) two attention sels of m-tile 8+(ew>>2)
        {
            int mta = 8 + (ew >> 2);
            int sb  = (ew & 3) * 2;
            do_mt(x, qk, mta, sb, sb + 2,
                  r0, Bnd, has_b, a_lo, a_hi, g4, t4, lane);
        }
        asm volatile("bar.arrive 2, 512;" ::: "memory");

        // 3) load extra A fragments for token tile 1
        uint32_t Ah1[6][4], Al1[6][4];
        load_efrag(x + (long)(m0tok + 16 + g4)*256 + 160, t4, Ah1, Al1);

        // 4) extra pipeline: tiles t == ew (mod 8), B read once, both m-tiles
        long tokA = m0tok + g4;
        #pragma unroll 1
        for (int t = ew; t < 34; t += 8) {
            float acc0[4] = {0.f,0.f,0.f,0.f};
            float acc1[4] = {0.f,0.f,0.f,0.f};
            #pragma unroll
            for (int ks = 0; ks < 6; ks++) {
                uint4 bv = g_EWf[(t*6 + ks)*32 + lane];
                mma16(acc0, Ah0[ks][0],Ah0[ks][1],Ah0[ks][2],Ah0[ks][3], bv.x, bv.y);
                mma16(acc0, Ah0[ks][0],Ah0[ks][1],Ah0[ks][2],Ah0[ks][3], bv.z, bv.w);
                mma16(acc0, Al0[ks][0],Al0[ks][1],Al0[ks][2],Al0[ks][3], bv.x, bv.y);
                mma16(acc1, Ah1[ks][0],Ah1[ks][1],Ah1[ks][2],Ah1[ks][3], bv.x, bv.y);
                mma16(acc1, Ah1[ks][0],Ah1[ks][1],Ah1[ks][2],Ah1[ks][3], bv.z, bv.w);
                mma16(acc1, Al1[ks][0],Al1[ks][1],Al1[ks][2],Al1[ks][3], bv.x, bv.y);
            }
            int u = t*8 + 2*t4;
            float bb0 = extra_b[u], bb1 = extra_b[u+1];
            *(float2*)&out[tokA*512 + 240 + u] =
                make_float2(acc0[0]+bb0, acc0[1]+bb1);
            *(float2*)&out[(tokA+8)*512 + 240 + u] =
                make_float2(acc0[2]+bb0, acc0[3]+bb1);
            *(float2*)&out[(tokA+16)*512 + 240 + u] =
                make_float2(acc1[0]+bb0, acc1[1]+bb1);
            *(float2*)&out[(tokA+24)*512 + 240 + u] =
                make_float2(acc1[2]+bb0, acc1[3]+bb1);
        }
        return;
    }

    // =============== A-WARPS: one full m-tile (8 sels), sync, scalar ========
    do_mt(x, qk, warp, 0, 8, r0, Bnd, has_b, a_lo, a_hi, g4, t4, lane);
    asm volatile("bar.sync 2, 512;" ::: "memory");

    const int z  = tid & 15;
    const int t0 = tid >> 4;             // 0..15

    // ---- softmax (vectorized float4 loads) ----------------------------------
    if (z < 10) {
        int h = z / 5, ii = z % 5;
        #pragma unroll
        for (int pick = 0; pick < 2; pick++) {
            int g = t0 + pick*16;
            const float* gb = qk + g*GRP;
            float4 qv[6];
            const float4* qp = (const float4*)(gb + ii*200 + h*24);
            #pragma unroll
            for (int d = 0; d < 6; d++) qv[d] = qp[d];
            float s[5]; float mx = -1e30f;
            #pragma unroll
            for (int j = 0; j < 5; j++) {
                const float4* kp = (const float4*)(gb + j*200 + 48 + h*24);
                float a = 0.f;
                #pragma unroll
                for (int d = 0; d < 6; d++) {
                    float4 kv = kp[d];
                    a = fmaf(qv[d].x, kv.x, a);
                    a = fmaf(qv[d].y, kv.y, a);
                    a = fmaf(qv[d].z, kv.z, a);
                    a = fmaf(qv[d].w, kv.w, a);
                }
                s[j] = a * 0.20412414523193154f;
                mx = fmaxf(mx, s[j]);
            }
            float sum = 0.f;
            #pragma unroll
            for (int j = 0; j < 5; j++) { s[j] = __expf(s[j]-mx); sum += s[j]; }
            float inv = 1.f / sum;
            #pragma unroll
            for (int j = 0; j < 5; j++) pb[g*52 + z*5 + j] = s[j]*inv;
        }
    }
    __syncwarp();   // pb producer/consumer are the same warp (t0 in {2w,2w+1})

    // ---- combine -> out cols [0,240) ----------------------------------------
    #pragma unroll 1
    for (int pick = 0; pick < 2; pick++) {
        int g = t0 + pick*16;
        const float* pg = pb + g*52;
        const float* vg = qk + g*GRP + 96;
        float pc[50];
        #pragma unroll
        for (int k = 0; k < 12; k++)
            *(float4*)&pc[k*4] = ((const float4*)pg)[k];
        pc[48] = pg[48]; pc[49] = pg[49];
        #pragma unroll
        for (int eidx = 0; eidx < 3; eidx++) {
            int e = z + 16*eidx;
            float vr[10];
            #pragma unroll
            for (int h = 0; h < 2; h++)
                #pragma unroll
                for (int j = 0; j < 5; j++)
                    vr[h*5+j] = vg[j*200 + h*48 + e];
            float ob = out_b[e];
            #pragma unroll
            for (int i = 0; i < 5; i++) {
                float acc = ob;
                #pragma unroll
                for (int h = 0; h < 2; h++)
                    #pragma unroll
                    for (int j = 0; j < 5; j++)
                        acc = fmaf(pc[(h*5+i)*5+j], vr[h*5+j], acc);
                out[(long)(m0tok+g)*512 + i*48 + e] = acc;
            }
        }
    }
}

extern "C" void kernel_launch(void* const* d_in, const int* in_sizes, int n_in,
                              void* d_out, int out_size)
{
    const float *x=0, *agg_W=0, *agg_b=0, *ipw=0, *ipb=0, *out_w=0, *out_b=0, *extra_w=0, *extra_b=0;
    for (int i = 0; i < n_in; i++) {
        switch (in_sizes[i]) {
            case 32*4096*256: x       = (const float*)d_in[i]; break;
            case 5*48*32:     agg_W   = (const float*)d_in[i]; break;
            case 5*48:        agg_b   = (const float*)d_in[i]; break;
            case 144*48:      ipw     = (const float*)d_in[i]; break;
            case 144:         ipb     = (const float*)d_in[i]; break;
            case 48*48:       out_w   = (const float*)d_in[i]; break;
            case 48:          out_b   = (const float*)d_in[i]; break;
            case 272*96:      extra_w = (const float*)d_in[i]; break;
            case 272:         extra_b = (const float*)d_in[i]; break;
            default: break;
        }
    }
    float* out = (float*)d_out;

    prep_kernel<<<28, PREP_T>>>(agg_W, agg_b, ipw, ipb, out_w, extra_w);

    const int smem_bytes = SM_WORDS * 4;   // 135680
    cudaFuncSetAttribute(main_kernel, cudaFuncAttributeMaxDynamicSharedMemorySize, smem_bytes);
    main_kernel<<<NBLOCKS, THREADS, smem_bytes>>>(x, extra_b, out_b, out);
}

// round 14
// speedup vs baseline: 1.2612x; 1.2612x over previous
#include <cuda_runtime.h>
#include <cuda_bf16.h>
#include <cstdint>

#define AA 5
#define THREADS 512
#define ROWS_PB 160
#define GROUPS_PB 32
#define NBLOCKS 4096

// ---------------- precomputed fused weights ---------------------------------
__device__ float    g_bqk  [AA][96];
__device__ float    g_bvo  [AA][96];
// extra weights, MMA-fragment layout: [(tile*6+ks)*32 + lane] = (bh0,bh1,bl0,bl1)
__device__ uint4    g_EWf[34*6*32];
// unified attention weights (qk cols 0-95, vo 96-191), fragment layout per a:
// [a*1536 + (n*2+ks)*32 + lane],  n = col-tile 0..23
__device__ uint4    g_WAf[AA*24*2*32];

__device__ __forceinline__ void split_bf16(float v, float& h, float& l) {
    h = __bfloat162float(__float2bfloat16_rn(v));
    l = v - h;
}

// pack: lo_e -> bits[15:0], hi_e -> bits[31:16]
__device__ __forceinline__ uint32_t packbf(float lo_e, float hi_e) {
    uint32_t r;
    asm("cvt.rn.bf16x2.f32 %0, %1, %2;" : "=r"(r) : "f"(hi_e), "f"(lo_e));
    return r;
}

__device__ __forceinline__ void mma16(float* d,
                                      uint32_t a0, uint32_t a1, uint32_t a2, uint32_t a3,
                                      uint32_t b0, uint32_t b1) {
    asm volatile("mma.sync.aligned.m16n8k16.row.col.f32.bf16.bf16.f32 "
                 "{%0,%1,%2,%3}, {%4,%5,%6,%7}, {%8,%9}, {%0,%1,%2,%3};"
                 : "+f"(d[0]), "+f"(d[1]), "+f"(d[2]), "+f"(d[3])
                 : "r"(a0), "r"(a1), "r"(a2), "r"(a3), "r"(b0), "r"(b1));
}

// ---------------------------- prep kernel ----------------------------------
#define PREP_T 256

// write one (col j_glob in 0..191, word w in 0..15) entry into g_WAf fragments
__device__ __forceinline__ void waf_write(int a, int j_glob, int w,
                                          float acc0, float acc1)
{
    float h0,l0,h1,l1;
    split_bf16(acc0, h0, l0); split_bf16(acc1, h1, l1);
    int n  = j_glob >> 3;
    int ks = w >> 3;
    int wp = w & 7;
    uint32_t* fr = (uint32_t*)&g_WAf[a*1536 + (n*2+ks)*32 + (j_glob&7)*4 + (wp&3)];
    fr[wp>>2]       = packbf(h0, h1);
    fr[2 + (wp>>2)] = packbf(l0, l1);
}

// blocks 0-9: qk (a = bid>>1, j-half = bid&1)
// blocks 10-19: vo ((a,h) = bid-10)
// blocks 20-27: extra (part = bid-20 of 8)
__global__ void prep_kernel(const float* __restrict__ agg_W,
                            const float* __restrict__ agg_b,
                            const float* __restrict__ ipw,
                            const float* __restrict__ ipb,
                            const float* __restrict__ out_w,
                            const float* __restrict__ extra_w)
{
    int bid = blockIdx.x;
    if (bid < 2*AA) {
        int a  = bid >> 1;
        int jh = bid & 1;                  // j in [jh*48, jh*48+48)
        __shared__ float sW[48*32];
        for (int i = threadIdx.x; i < 48*32; i += PREP_T)
            sW[i] = agg_W[a*1536 + i];
        __syncthreads();
        for (int o = threadIdx.x; o < 48*16; o += PREP_T) {
            int j = jh*48 + (o >> 4), w = o & 15;
            float acc0 = 0.f, acc1 = 0.f;
            #pragma unroll 4
            for (int e = 0; e < 48; e++) {
                float wv = ipw[j*48+e];
                acc0 += wv * sW[e*32 + 2*w];
                acc1 += wv * sW[e*32 + 2*w+1];
            }
            waf_write(a, j, w, acc0, acc1);
        }
        for (int jj = threadIdx.x; jj < 48; jj += PREP_T) {
            int j = jh*48 + jj;
            float acc = ipb[j];
            for (int e = 0; e < 48; e++)
                acc += ipw[j*48+e] * agg_b[a*48+e];
            g_bqk[a][j] = acc;
        }
    } else if (bid < 2*AA + 2*AA) {
        int a = (bid - 2*AA) >> 1;
        int h = (bid - 2*AA) & 1;
        __shared__ float sW[48*32];
        __shared__ float Wv[24][32];
        __shared__ float bv[24];
        for (int i = threadIdx.x; i < 48*32; i += PREP_T)
            sW[i] = agg_W[a*1536 + i];
        __syncthreads();
        for (int o = threadIdx.x; o < 24*32; o += PREP_T) {
            int d = o >> 5, c = o & 31;
            int row = 96 + h*24 + d;
            float acc = 0.f;
            #pragma unroll 4
            for (int e = 0; e < 48; e++)
                acc += ipw[row*48+e] * sW[e*32 + c];
            Wv[d][c] = acc;
        }
        for (int d = threadIdx.x; d < 24; d += PREP_T) {
            int row = 96 + h*24 + d;
            float acc = ipb[row];
            for (int e = 0; e < 48; e++)
                acc += ipw[row*48+e] * agg_b[a*48+e];
            bv[d] = acc;
        }
        __syncthreads();
        for (int o = threadIdx.x; o < 48*16; o += PREP_T) {
            int e = o >> 4, w = o & 15;
            float acc0 = 0.f, acc1 = 0.f;
            #pragma unroll
            for (int d = 0; d < 24; d++) {
                float ow = out_w[e*48 + h*24 + d];
                acc0 += Wv[d][2*w]   * ow;
                acc1 += Wv[d][2*w+1] * ow;
            }
            waf_write(a, 96 + h*48 + e, w, acc0, acc1);
        }
        for (int e = threadIdx.x; e < 48; e += PREP_T) {
            float acc = 0.f;
            for (int d = 0; d < 24; d++)
                acc += bv[d] * out_w[e*48 + h*24 + d];
            g_bvo[a][h*48 + e] = acc;
        }
    } else {
        // extra_w -> fragment layout; 8 blocks cover 34*6*32 = 6528 uint4
        int part = bid - 4*AA;                // 0..7
        int beg = part * 816;
        int end = beg + 816;
        for (int o = beg + threadIdx.x; o < end; o += PREP_T) {
            int lane = o & 31;
            int tk   = o >> 5;
            int ks   = tk % 6;
            int t    = tk / 6;
            int g4   = lane >> 2, t4 = lane & 3;
            int row  = t*8 + g4;              // output col (0..271)
            int w0   = ks*8 + t4;
            float v00 = extra_w[row*96 + 2*w0];
            float v01 = extra_w[row*96 + 2*w0 + 1];
            float v10 = extra_w[row*96 + 2*(w0+4)];
            float v11 = extra_w[row*96 + 2*(w0+4) + 1];
            float h00,l00,h01,l01,h10,l10,h11,l11;
            split_bf16(v00,h00,l00); split_bf16(v01,h01,l01);
            split_bf16(v10,h10,l10); split_bf16(v11,h11,l11);
            g_EWf[o] = make_uint4(packbf(h00,h01), packbf(h10,h11),
                                  packbf(l00,l01), packbf(l10,l11));
        }
    }
}

// ---------------------------- main kernel ----------------------------------
// Shared layout (32-bit words):
//   qk : fp32 D[160x192]; row r at (r/5)*1008 + (r%5)*200 (16B aligned)
//   pb : 32 x 52 fp32 softmax probs
#define GRP 1008
#define SM_QK  0
#define SM_PB  32256
#define SM_WORDS 33920           // 135680 bytes

__device__ __forceinline__ long row_xoff(int r)
{
    int a  = (r >> 12) % 5;
    int tx = (r / 20480) * 4096 + (r & 4095);
    return (long)tx * 256 + a * 32;
}

// load the A fragments (2 k-steps) for m-tile mt from global x
__device__ __forceinline__ void load_afrag(const float* __restrict__ x,
                                           int r0, int mt, int g4, int t4,
                                           uint32_t ah[2][4], uint32_t al[2][4])
{
    const float* xA = x + row_xoff(r0 + mt*16 + g4);
    const float* xB = x + row_xoff(r0 + mt*16 + g4 + 8);
    #pragma unroll
    for (int ks = 0; ks < 2; ks++) {
        int c0 = (ks*8 + t4)*2;
        float2 vA0 = *(const float2*)(xA + c0);
        float2 vA2 = *(const float2*)(xA + c0 + 8);
        float2 vB0 = *(const float2*)(xB + c0);
        float2 vB2 = *(const float2*)(xB + c0 + 8);
        float h0,l0,h1,l1;
        split_bf16(vA0.x,h0,l0); split_bf16(vA0.y,h1,l1);
        ah[ks][0] = packbf(h0,h1); al[ks][0] = packbf(l0,l1);
        split_bf16(vB0.x,h0,l0); split_bf16(vB0.y,h1,l1);
        ah[ks][1] = packbf(h0,h1); al[ks][1] = packbf(l0,l1);
        split_bf16(vA2.x,h0,l0); split_bf16(vA2.y,h1,l1);
        ah[ks][2] = packbf(h0,h1); al[ks][2] = packbf(l0,l1);
        split_bf16(vB2.x,h0,l0); split_bf16(vB2.y,h1,l1);
        ah[ks][3] = packbf(h0,h1); al[ks][3] = packbf(l0,l1);
    }
}

// process attention GEMM sels [sbeg,send) of ONE m-tile mt:
// sel -> half=sel>>2 (0 qk | 1 vo), ng3=sel&3 (24-col group)
__device__ __forceinline__ void do_mt(const float* __restrict__ x,
                                      float* __restrict__ qk,
                                      int mt, int sbeg, int send,
                                      int r0, int Bnd, bool has_b,
                                      int a_lo, int a_hi,
                                      int g4, int t4, int lane)
{
    bool hiset = has_b && (r0 + mt*16) >= Bnd;
    int a_t = hiset ? a_hi : a_lo;
    uint32_t ah[2][4], al[2][4];
    load_afrag(x, r0, mt, g4, t4, ah, al);
    const uint4* wf = g_WAf + a_t*1536;

    int R0 = mt*16 + g4;
    int R1 = R0 + 8;
    int off0 = (R0/5)*GRP + (R0%5)*200;
    int off1 = (R1/5)*GRP + (R1%5)*200;

    #pragma unroll 1
    for (int sel = sbeg; sel < send; sel++) {
        int half = sel >> 2, ng3 = sel & 3;
        float acc[3][4];
        #pragma unroll
        for (int nj = 0; nj < 3; nj++)
            #pragma unroll
            for (int q = 0; q < 4; q++) acc[nj][q] = 0.f;
        #pragma unroll
        for (int ks = 0; ks < 2; ks++) {
            #pragma unroll
            for (int nj = 0; nj < 3; nj++) {
                int n = half*12 + ng3*3 + nj;
                uint4 bv = wf[(n*2+ks)*32 + lane];
                mma16(acc[nj], ah[ks][0],ah[ks][1],ah[ks][2],ah[ks][3], bv.x, bv.y);
                mma16(acc[nj], ah[ks][0],ah[ks][1],ah[ks][2],ah[ks][3], bv.z, bv.w);
                mma16(acc[nj], al[ks][0],al[ks][1],al[ks][2],al[ks][3], bv.x, bv.y);
            }
        }
        const float* bias = half ? g_bvo[a_t] : g_bqk[a_t];
        #pragma unroll
        for (int nj = 0; nj < 3; nj++) {
            int c96 = ng3*24 + nj*8 + 2*t4;
            float b0 = bias[c96], b1 = bias[c96+1];
            int col = half*96 + c96;
            *(float2*)&qk[off0 + col] = make_float2(acc[nj][0]+b0, acc[nj][1]+b1);
            *(float2*)&qk[off1 + col] = make_float2(acc[nj][2]+b0, acc[nj][3]+b1);
        }
    }
}

__global__ void __launch_bounds__(THREADS, 1)
main_kernel(const float* __restrict__ x,
            const float* __restrict__ extra_b,
            const float* __restrict__ out_b,
            float* __restrict__ out)
{
    extern __shared__ float sm[];
    float* qk = sm + SM_QK;
    float* pb = sm + SM_PB;

    const int tid  = threadIdx.x;
    const int lane = tid & 31;
    const int warp = tid >> 5;       // 0..15
    const int g4   = lane >> 2;
    const int t4   = lane & 3;

    const int r0    = blockIdx.x * ROWS_PB;
    const int m0tok = blockIdx.x * GROUPS_PB;

    const int  blk4k = r0 >> 12;
    const int  a_lo  = blk4k % 5;
    const int  Bnd   = (blk4k + 1) << 12;
    const bool has_b = (r0 + ROWS_PB) > Bnd;
    const int  a_hi  = has_b ? ((a_lo + 1) % 5) : a_lo;

    if (warp >= 8) {
        // =============== E-WARPS =============================================
        // 1) prefetch extra-pipeline A fragments (DRAM loads in flight early)
        int ew = warp - 8;               // 0..7
        int mt = ew & 1;
        int qw = ew >> 1;                // col-tile residue class mod 4

        uint32_t Ah[6][4], Al[6][4];
        const float* xb = x + (long)(m0tok + mt*16 + g4)*256 + 160;
        #pragma unroll
        for (int ks = 0; ks < 6; ks++) {
            int c0 = (ks*8 + t4)*2;
            float2 v0 = *(const float2*)(xb + c0);
            float2 v2 = *(const float2*)(xb + c0 + 8);
            float2 v1 = *(const float2*)(xb + 2048 + c0);
            float2 v3 = *(const float2*)(xb + 2048 + c0 + 8);
            float h0,l0,h1,l1;
            split_bf16(v0.x,h0,l0); split_bf16(v0.y,h1,l1);
            Ah[ks][0] = packbf(h0,h1); Al[ks][0] = packbf(l0,l1);
            split_bf16(v1.x,h0,l0); split_bf16(v1.y,h1,l1);
            Ah[ks][1] = packbf(h0,h1); Al[ks][1] = packbf(l0,l1);
            split_bf16(v2.x,h0,l0); split_bf16(v2.y,h1,l1);
            Ah[ks][2] = packbf(h0,h1); Al[ks][2] = packbf(l0,l1);
            split_bf16(v3.x,h0,l0); split_bf16(v3.y,h1,l1);
            Ah[ks][3] = packbf(h0,h1); Al[ks][3] = packbf(l0,l1);
        }

        // 2) two attention sels of m-tile 8+(ew>>2)
        {
            int mta = 8 + (ew >> 2);
            int sb  = (ew & 3) * 2;
            do_mt(x, qk, mta, sb, sb + 2,
                  r0, Bnd, has_b, a_lo, a_hi, g4, t4, lane);
        }
        asm volatile("bar.arrive 2, 512;" ::: "memory");

        // 3) extra pipeline
        long tokA = m0tok + mt*16 + g4;
        #pragma unroll 1
        for (int t = qw; t < 34; t += 4) {
            float acc[4] = {0.f, 0.f, 0.f, 0.f};
            #pragma unroll
            for (int ks = 0; ks < 6; ks++) {
                uint4 bv = g_EWf[(t*6 + ks)*32 + lane];
                mma16(acc, Ah[ks][0],Ah[ks][1],Ah[ks][2],Ah[ks][3], bv.x, bv.y);
                mma16(acc, Ah[ks][0],Ah[ks][1],Ah[ks][2],Ah[ks][3], bv.z, bv.w);
                mma16(acc, Al[ks][0],Al[ks][1],Al[ks][2],Al[ks][3], bv.x, bv.y);
            }
            int u = t*8 + 2*t4;
            float bb0 = extra_b[u], bb1 = extra_b[u+1];
            *(float2*)&out[tokA*512 + 240 + u] =
                make_float2(acc[0]+bb0, acc[1]+bb1);
            *(float2*)&out[(tokA+8)*512 + 240 + u] =
                make_float2(acc[2]+bb0, acc[3]+bb1);
        }
        return;
    }

    // =============== A-WARPS: one full m-tile (8 sels), sync, scalar ========
    do_mt(x, qk, warp, 0, 8, r0, Bnd, has_b, a_lo, a_hi, g4, t4, lane);
    asm volatile("bar.sync 2, 512;" ::: "memory");

    const int z  = tid & 15;
    const int t0 = tid >> 4;             // 0..15

    // ---- softmax (vectorized float4 loads) ----------------------------------
    if (z < 10) {
        int h = z / 5, ii = z % 5;
        #pragma unroll
        for (int pick = 0; pick < 2; pick++) {
            int g = t0 + pick*16;
            const float* gb = qk + g*GRP;
            float4 qv[6];
            const float4* qp = (const float4*)(gb + ii*200 + h*24);
            #pragma unroll
            for (int d = 0; d < 6; d++) qv[d] = qp[d];
            float s[5]; float mx = -1e30f;
            #pragma unroll
            for (int j = 0; j < 5; j++) {
                const float4* kp = (const float4*)(gb + j*200 + 48 + h*24);
                float a = 0.f;
                #pragma unroll
                for (int d = 0; d < 6; d++) {
                    float4 kv = kp[d];
                    a = fmaf(qv[d].x, kv.x, a);
                    a = fmaf(qv[d].y, kv.y, a);
                    a = fmaf(qv[d].z, kv.z, a);
                    a = fmaf(qv[d].w, kv.w, a);
                }
                s[j] = a * 0.20412414523193154f;
                mx = fmaxf(mx, s[j]);
            }
            float sum = 0.f;
            #pragma unroll
            for (int j = 0; j < 5; j++) { s[j] = __expf(s[j]-mx); sum += s[j]; }
            float inv = 1.f / sum;
            #pragma unroll
            for (int j = 0; j < 5; j++) pb[g*52 + z*5 + j] = s[j]*inv;
        }
    }
    __syncwarp();   // pb producer/consumer are the same warp (t0 in {2w,2w+1})

    // ---- combine -> out cols [0,240) ----------------------------------------
    #pragma unroll 1
    for (int pick = 0; pick < 2; pick++) {
        int g = t0 + pick*16;
        const float* pg = pb + g*52;
        const float* vg = qk + g*GRP + 96;
        float pc[50];
        #pragma unroll
        for (int k = 0; k < 12; k++)
            *(float4*)&pc[k*4] = ((const float4*)pg)[k];
        pc[48] = pg[48]; pc[49] = pg[49];
        #pragma unroll
        for (int eidx = 0; eidx < 3; eidx++) {
            int e = z + 16*eidx;
            float vr[10];
            #pragma unroll
            for (int h = 0; h < 2; h++)
                #pragma unroll
                for (int j = 0; j < 5; j++)
                    vr[h*5+j] = vg[j*200 + h*48 + e];
            float ob = out_b[e];
            #pragma unroll
            for (int i = 0; i < 5; i++) {
                float acc = ob;
                #pragma unroll
                for (int h = 0; h < 2; h++)
                    #pragma unroll
                    for (int j = 0; j < 5; j++)
                        acc = fmaf(pc[(h*5+i)*5+j], vr[h*5+j], acc);
                out[(long)(m0tok+g)*512 + i*48 + e] = acc;
            }
        }
    }
}

extern "C" void kernel_launch(void* const* d_in, const int* in_sizes, int n_in,
                              void* d_out, int out_size)
{
    const float *x=0, *agg_W=0, *agg_b=0, *ipw=0, *ipb=0, *out_w=0, *out_b=0, *extra_w=0, *extra_b=0;
    for (int i = 0; i < n_in; i++) {
        switch (in_sizes[i]) {
            case 32*4096*256: x       = (const float*)d_in[i]; break;
            case 5*48*32:     agg_W   = (const float*)d_in[i]; break;
            case 5*48:        agg_b   = (const float*)d_in[i]; break;
            case 144*48:      ipw     = (const float*)d_in[i]; break;
            case 144:         ipb     = (const float*)d_in[i]; break;
            case 48*48:       out_w   = (const float*)d_in[i]; break;
            case 48:          out_b   = (const float*)d_in[i]; break;
            case 272*96:      extra_w = (const float*)d_in[i]; break;
            case 272:         extra_b = (const float*)d_in[i]; break;
            default: break;
        }
    }
    float* out = (float*)d_out;

    prep_kernel<<<28, PREP_T>>>(agg_W, agg_b, ipw, ipb, out_w, extra_w);

    const int smem_bytes = SM_WORDS * 4;   // 135680
    cudaFuncSetAttribute(main_kernel, cudaFuncAttributeMaxDynamicSharedMemorySize, smem_bytes);
    main_kernel<<<NBLOCKS, THREADS, smem_bytes>>>(x, extra_b, out_b, out);
}

// round 15
// speedup vs baseline: 1.4884x; 1.1801x over previous
#include <cuda_runtime.h>
#include <cuda_fp16.h>
#include <cstdint>

#define AA 5
#define THREADS 512
#define ROWS_PB 160
#define GROUPS_PB 32
#define NBLOCKS 4096

// ---------------- precomputed fused weights (fp16 fragments) ----------------
__device__ float    g_bqk  [AA][96];
__device__ float    g_bvo  [AA][96];
// extra weights, MMA-fragment layout: [(tile*6+ks)*32 + lane] = (b0,b1) fp16x2
__device__ uint2    g_EWf[34*6*32];
// unified attention weights (qk cols 0-95, vo 96-191), fragment layout per a:
// [a*1536 + (n*2+ks)*32 + lane],  n = col-tile 0..23
__device__ uint2    g_WAf[AA*24*2*32];

// pack: lo_e -> bits[15:0], hi_e -> bits[31:16]   (fp16x2)
__device__ __forceinline__ uint32_t packhf(float lo_e, float hi_e) {
    uint32_t r;
    asm("cvt.rn.f16x2.f32 %0, %1, %2;" : "=r"(r) : "f"(hi_e), "f"(lo_e));
    return r;
}

__device__ __forceinline__ void mma16(float* d,
                                      uint32_t a0, uint32_t a1, uint32_t a2, uint32_t a3,
                                      uint32_t b0, uint32_t b1) {
    asm volatile("mma.sync.aligned.m16n8k16.row.col.f32.f16.f16.f32 "
                 "{%0,%1,%2,%3}, {%4,%5,%6,%7}, {%8,%9}, {%0,%1,%2,%3};"
                 : "+f"(d[0]), "+f"(d[1]), "+f"(d[2]), "+f"(d[3])
                 : "r"(a0), "r"(a1), "r"(a2), "r"(a3), "r"(b0), "r"(b1));
}

// ---------------------------- prep kernel ----------------------------------
#define PREP_T 256

// write one (col j_glob in 0..191, word w in 0..15) entry into g_WAf fragments
__device__ __forceinline__ void waf_write(int a, int j_glob, int w,
                                          float acc0, float acc1)
{
    int n  = j_glob >> 3;
    int ks = w >> 3;
    int wp = w & 7;
    uint32_t* fr = (uint32_t*)&g_WAf[a*1536 + (n*2+ks)*32 + (j_glob&7)*4 + (wp&3)];
    fr[wp>>2] = packhf(acc0, acc1);
}

// blocks 0-9: qk (a = bid>>1, j-half = bid&1)
// blocks 10-19: vo ((a,h) = bid-10)
// blocks 20-27: extra (part = bid-20 of 8)
__global__ void prep_kernel(const float* __restrict__ agg_W,
                            const float* __restrict__ agg_b,
                            const float* __restrict__ ipw,
                            const float* __restrict__ ipb,
                            const float* __restrict__ out_w,
                            const float* __restrict__ extra_w)
{
    int bid = blockIdx.x;
    if (bid < 2*AA) {
        int a  = bid >> 1;
        int jh = bid & 1;                  // j in [jh*48, jh*48+48)
        __shared__ float sW[48*32];
        for (int i = threadIdx.x; i < 48*32; i += PREP_T)
            sW[i] = agg_W[a*1536 + i];
        __syncthreads();
        for (int o = threadIdx.x; o < 48*16; o += PREP_T) {
            int j = jh*48 + (o >> 4), w = o & 15;
            float acc0 = 0.f, acc1 = 0.f;
            #pragma unroll 4
            for (int e = 0; e < 48; e++) {
                float wv = ipw[j*48+e];
                acc0 += wv * sW[e*32 + 2*w];
                acc1 += wv * sW[e*32 + 2*w+1];
            }
            waf_write(a, j, w, acc0, acc1);
        }
        for (int jj = threadIdx.x; jj < 48; jj += PREP_T) {
            int j = jh*48 + jj;
            float acc = ipb[j];
            for (int e = 0; e < 48; e++)
                acc += ipw[j*48+e] * agg_b[a*48+e];
            g_bqk[a][j] = acc;
        }
    } else if (bid < 2*AA + 2*AA) {
        int a = (bid - 2*AA) >> 1;
        int h = (bid - 2*AA) & 1;
        __shared__ float sW[48*32];
        __shared__ float Wv[24][32];
        __shared__ float bv[24];
        for (int i = threadIdx.x; i < 48*32; i += PREP_T)
            sW[i] = agg_W[a*1536 + i];
        __syncthreads();
        for (int o = threadIdx.x; o < 24*32; o += PREP_T) {
            int d = o >> 5, c = o & 31;
            int row = 96 + h*24 + d;
            float acc = 0.f;
            #pragma unroll 4
            for (int e = 0; e < 48; e++)
                acc += ipw[row*48+e] * sW[e*32 + c];
            Wv[d][c] = acc;
        }
        for (int d = threadIdx.x; d < 24; d += PREP_T) {
            int row = 96 + h*24 + d;
            float acc = ipb[row];
            for (int e = 0; e < 48; e++)
                acc += ipw[row*48+e] * agg_b[a*48+e];
            bv[d] = acc;
        }
        __syncthreads();
        for (int o = threadIdx.x; o < 48*16; o += PREP_T) {
            int e = o >> 4, w = o & 15;
            float acc0 = 0.f, acc1 = 0.f;
            #pragma unroll
            for (int d = 0; d < 24; d++) {
                float ow = out_w[e*48 + h*24 + d];
                acc0 += Wv[d][2*w]   * ow;
                acc1 += Wv[d][2*w+1] * ow;
            }
            waf_write(a, 96 + h*48 + e, w, acc0, acc1);
        }
        for (int e = threadIdx.x; e < 48; e += PREP_T) {
            float acc = 0.f;
            for (int d = 0; d < 24; d++)
                acc += bv[d] * out_w[e*48 + h*24 + d];
            g_bvo[a][h*48 + e] = acc;
        }
    } else {
        // extra_w -> fragment layout; 8 blocks cover 34*6*32 = 6528 uint2
        int part = bid - 4*AA;                // 0..7
        int beg = part * 816;
        int end = beg + 816;
        for (int o = beg + threadIdx.x; o < end; o += PREP_T) {
            int lane = o & 31;
            int tk   = o >> 5;
            int ks   = tk % 6;
            int t    = tk / 6;
            int g4   = lane >> 2, t4 = lane & 3;
            int row  = t*8 + g4;              // output col (0..271)
            int w0   = ks*8 + t4;
            float v00 = extra_w[row*96 + 2*w0];
            float v01 = extra_w[row*96 + 2*w0 + 1];
            float v10 = extra_w[row*96 + 2*(w0+4)];
            float v11 = extra_w[row*96 + 2*(w0+4) + 1];
            g_EWf[o] = make_uint2(packhf(v00, v01), packhf(v10, v11));
        }
    }
}

// ---------------------------- main kernel ----------------------------------
// Shared layout (32-bit words):
//   qk : fp32 D[160x192]; row r at (r/5)*1008 + (r%5)*200 (16B aligned)
//   pb : 32 x 52 fp32 softmax probs
#define GRP 1008
#define SM_QK  0
#define SM_PB  32256
#define SM_WORDS 33920           // 135680 bytes

__device__ __forceinline__ long row_xoff(int r)
{
    int a  = (r >> 12) % 5;
    int tx = (r / 20480) * 4096 + (r & 4095);
    return (long)tx * 256 + a * 32;
}

// load the A fragments (2 k-steps) for m-tile mt from global x (fp16 pack)
__device__ __forceinline__ void load_afrag(const float* __restrict__ x,
                                           int r0, int mt, int g4, int t4,
                                           uint32_t ah[2][4])
{
    const float* xA = x + row_xoff(r0 + mt*16 + g4);
    const float* xB = x + row_xoff(r0 + mt*16 + g4 + 8);
    #pragma unroll
    for (int ks = 0; ks < 2; ks++) {
        int c0 = (ks*8 + t4)*2;
        float2 vA0 = *(const float2*)(xA + c0);
        float2 vA2 = *(const float2*)(xA + c0 + 8);
        float2 vB0 = *(const float2*)(xB + c0);
        float2 vB2 = *(const float2*)(xB + c0 + 8);
        ah[ks][0] = packhf(vA0.x, vA0.y);
        ah[ks][1] = packhf(vB0.x, vB0.y);
        ah[ks][2] = packhf(vA2.x, vA2.y);
        ah[ks][3] = packhf(vB2.x, vB2.y);
    }
}

// process attention GEMM sels [sbeg,send) of ONE m-tile mt:
// sel -> half=sel>>2 (0 qk | 1 vo), ng3=sel&3 (24-col group)
__device__ __forceinline__ void do_mt(const float* __restrict__ x,
                                      float* __restrict__ qk,
                                      int mt, int sbeg, int send,
                                      int r0, int Bnd, bool has_b,
                                      int a_lo, int a_hi,
                                      int g4, int t4, int lane)
{
    bool hiset = has_b && (r0 + mt*16) >= Bnd;
    int a_t = hiset ? a_hi : a_lo;
    uint32_t ah[2][4];
    load_afrag(x, r0, mt, g4, t4, ah);
    const uint2* wf = g_WAf + a_t*1536;

    int R0 = mt*16 + g4;
    int R1 = R0 + 8;
    int off0 = (R0/5)*GRP + (R0%5)*200;
    int off1 = (R1/5)*GRP + (R1%5)*200;

    #pragma unroll 1
    for (int sel = sbeg; sel < send; sel++) {
        int half = sel >> 2, ng3 = sel & 3;
        float acc[3][4];
        #pragma unroll
        for (int nj = 0; nj < 3; nj++)
            #pragma unroll
            for (int q = 0; q < 4; q++) acc[nj][q] = 0.f;
        #pragma unroll
        for (int ks = 0; ks < 2; ks++) {
            #pragma unroll
            for (int nj = 0; nj < 3; nj++) {
                int n = half*12 + ng3*3 + nj;
                uint2 bv = wf[(n*2+ks)*32 + lane];
                mma16(acc[nj], ah[ks][0],ah[ks][1],ah[ks][2],ah[ks][3], bv.x, bv.y);
            }
        }
        const float* bias = half ? g_bvo[a_t] : g_bqk[a_t];
        #pragma unroll
        for (int nj = 0; nj < 3; nj++) {
            int c96 = ng3*24 + nj*8 + 2*t4;
            float b0 = bias[c96], b1 = bias[c96+1];
            int col = half*96 + c96;
            *(float2*)&qk[off0 + col] = make_float2(acc[nj][0]+b0, acc[nj][1]+b1);
            *(float2*)&qk[off1 + col] = make_float2(acc[nj][2]+b0, acc[nj][3]+b1);
        }
    }
}

__global__ void __launch_bounds__(THREADS, 1)
main_kernel(const float* __restrict__ x,
            const float* __restrict__ extra_b,
            const float* __restrict__ out_b,
            float* __restrict__ out)
{
    extern __shared__ float sm[];
    float* qk = sm + SM_QK;
    float* pb = sm + SM_PB;

    const int tid  = threadIdx.x;
    const int lane = tid & 31;
    const int warp = tid >> 5;       // 0..15
    const int g4   = lane >> 2;
    const int t4   = lane & 3;

    const int r0    = blockIdx.x * ROWS_PB;
    const int m0tok = blockIdx.x * GROUPS_PB;

    const int  blk4k = r0 >> 12;
    const int  a_lo  = blk4k % 5;
    const int  Bnd   = (blk4k + 1) << 12;
    const bool has_b = (r0 + ROWS_PB) > Bnd;
    const int  a_hi  = has_b ? ((a_lo + 1) % 5) : a_lo;

    if (warp >= 8) {
        // =============== E-WARPS =============================================
        // 1) prefetch extra-pipeline A fragments (DRAM loads in flight early)
        int ew = warp - 8;               // 0..7
        int mt = ew & 1;
        int qw = ew >> 1;                // col-tile residue class mod 4

        uint32_t Ah[6][4];
        const float* xb = x + (long)(m0tok + mt*16 + g4)*256 + 160;
        #pragma unroll
        for (int ks = 0; ks < 6; ks++) {
            int c0 = (ks*8 + t4)*2;
            float2 v0 = *(const float2*)(xb + c0);
            float2 v2 = *(const float2*)(xb + c0 + 8);
            float2 v1 = *(const float2*)(xb + 2048 + c0);
            float2 v3 = *(const float2*)(xb + 2048 + c0 + 8);
            Ah[ks][0] = packhf(v0.x, v0.y);
            Ah[ks][1] = packhf(v1.x, v1.y);
            Ah[ks][2] = packhf(v2.x, v2.y);
            Ah[ks][3] = packhf(v3.x, v3.y);
        }

        // 2) two attention sels of m-tile 8+(ew>>2)
        {
            int mta = 8 + (ew >> 2);
            int sb  = (ew & 3) * 2;
            do_mt(x, qk, mta, sb, sb + 2,
                  r0, Bnd, has_b, a_lo, a_hi, g4, t4, lane);
        }
        asm volatile("bar.arrive 2, 512;" ::: "memory");

        // 3) extra pipeline
        long tokA = m0tok + mt*16 + g4;
        #pragma unroll 1
        for (int t = qw; t < 34; t += 4) {
            float acc[4] = {0.f, 0.f, 0.f, 0.f};
            #pragma unroll
            for (int ks = 0; ks < 6; ks++) {
                uint2 bv = g_EWf[(t*6 + ks)*32 + lane];
                mma16(acc, Ah[ks][0],Ah[ks][1],Ah[ks][2],Ah[ks][3], bv.x, bv.y);
            }
            int u = t*8 + 2*t4;
            float bb0 = extra_b[u], bb1 = extra_b[u+1];
            *(float2*)&out[tokA*512 + 240 + u] =
                make_float2(acc[0]+bb0, acc[1]+bb1);
            *(float2*)&out[(tokA+8)*512 + 240 + u] =
                make_float2(acc[2]+bb0, acc[3]+bb1);
        }
        return;
    }

    // =============== A-WARPS: one full m-tile (8 sels), sync, scalar ========
    do_mt(x, qk, warp, 0, 8, r0, Bnd, has_b, a_lo, a_hi, g4, t4, lane);
    asm volatile("bar.sync 2, 512;" ::: "memory");

    const int z  = tid & 15;
    const int t0 = tid >> 4;             // 0..15

    // ---- softmax (vectorized float4 loads) ----------------------------------
    if (z < 10) {
        int h = z / 5, ii = z % 5;
        #pragma unroll
        for (int pick = 0; pick < 2; pick++) {
            int g = t0 + pick*16;
            const float* gb = qk + g*GRP;
            float4 qv[6];
            const float4* qp = (const float4*)(gb + ii*200 + h*24);
            #pragma unroll
            for (int d = 0; d < 6; d++) qv[d] = qp[d];
            float s[5]; float mx = -1e30f;
            #pragma unroll
            for (int j = 0; j < 5; j++) {
                const float4* kp = (const float4*)(gb + j*200 + 48 + h*24);
                float a = 0.f;
                #pragma unroll
                for (int d = 0; d < 6; d++) {
                    float4 kv = kp[d];
                    a = fmaf(qv[d].x, kv.x, a);
                    a = fmaf(qv[d].y, kv.y, a);
                    a = fmaf(qv[d].z, kv.z, a);
                    a = fmaf(qv[d].w, kv.w, a);
                }
                s[j] = a * 0.20412414523193154f;
                mx = fmaxf(mx, s[j]);
            }
            float sum = 0.f;
            #pragma unroll
            for (int j = 0; j < 5; j++) { s[j] = __expf(s[j]-mx); sum += s[j]; }
            float inv = 1.f / sum;
            #pragma unroll
            for (int j = 0; j < 5; j++) pb[g*52 + z*5 + j] = s[j]*inv;
        }
    }
    __syncwarp();   // pb producer/consumer are the same warp (t0 in {2w,2w+1})

    // ---- combine -> out cols [0,240) ----------------------------------------
    #pragma unroll 1
    for (int pick = 0; pick < 2; pick++) {
        int g = t0 + pick*16;
        const float* pg = pb + g*52;
        const float* vg = qk + g*GRP + 96;
        float pc[50];
        #pragma unroll
        for (int k = 0; k < 12; k++)
            *(float4*)&pc[k*4] = ((const float4*)pg)[k];
        pc[48] = pg[48]; pc[49] = pg[49];
        #pragma unroll
        for (int eidx = 0; eidx < 3; eidx++) {
            int e = z + 16*eidx;
            float vr[10];
            #pragma unroll
            for (int h = 0; h < 2; h++)
                #pragma unroll
                for (int j = 0; j < 5; j++)
                    vr[h*5+j] = vg[j*200 + h*48 + e];
            float ob = out_b[e];
            #pragma unroll
            for (int i = 0; i < 5; i++) {
                float acc = ob;
                #pragma unroll
                for (int h = 0; h < 2; h++)
                    #pragma unroll
                    for (int j = 0; j < 5; j++)
                        acc = fmaf(pc[(h*5+i)*5+j], vr[h*5+j], acc);
                out[(long)(m0tok+g)*512 + i*48 + e] = acc;
            }
        }
    }
}

extern "C" void kernel_launch(void* const* d_in, const int* in_sizes, int n_in,
                              void* d_out, int out_size)
{
    const float *x=0, *agg_W=0, *agg_b=0, *ipw=0, *ipb=0, *out_w=0, *out_b=0, *extra_w=0, *extra_b=0;
    for (int i = 0; i < n_in; i++) {
        switch (in_sizes[i]) {
            case 32*4096*256: x       = (const float*)d_in[i]; break;
            case 5*48*32:     agg_W   = (const float*)d_in[i]; break;
            case 5*48:        agg_b   = (const float*)d_in[i]; break;
            case 144*48:      ipw     = (const float*)d_in[i]; break;
            case 144:         ipb     = (const float*)d_in[i]; break;
            case 48*48:       out_w   = (const float*)d_in[i]; break;
            case 48:          out_b   = (const float*)d_in[i]; break;
            case 272*96:      extra_w = (const float*)d_in[i]; break;
            case 272:         extra_b = (const float*)d_in[i]; break;
            default: break;
        }
    }
    float* out = (float*)d_out;

    prep_kernel<<<28, PREP_T>>>(agg_W, agg_b, ipw, ipb, out_w, extra_w);

    const int smem_bytes = SM_WORDS * 4;   // 135680
    cudaFuncSetAttribute(main_kernel, cudaFuncAttributeMaxDynamicSharedMemorySize, smem_bytes);
    main_kernel<<<NBLOCKS, THREADS, smem_bytes>>>(x, extra_b, out_b, out);
}